// round 5
// baseline (speedup 1.0000x reference)
#include <cuda_runtime.h>
#include <cuda_bf16.h>
#include <cstdint>

// CostVolume via mma.sync bf16-split GEMM (HMMA path; tcgen05 unavailable:
// harness compiles through virtual arch compute_103).
//
// out[b,h,j,i] = (1/128) * sum_c L[b,h,j,c]*R[b,h,j-i,c], j>=i else 0.
// Per CTA (bh, kt): D[m<128][n<64] = sum_c L[kt*64+m][c]*R[kt*64+n][c];
// out(j=kt*64+m, i=m-n) valid iff 0<=i<64, each covered exactly once.
// fp32 accuracy: A=Ah+Al, B=Bh+Bl (bf16), D = Ah*Bh + Al*Bh + Ah*Bl.

#define WW 320
#define CC 128
#define DD 64
#define ROWB 272   // 136 bf16 row stride: 128 data + pad -> conflict-free ldmatrix

#define OFF_AH 0
#define OFF_AL (128 * ROWB)
#define OFF_BH (OFF_AL + 128 * ROWB)
#define OFF_BL (OFF_BH + 64 * ROWB)
#define SMEM_TOTAL (OFF_BL + 64 * ROWB) // 104448

__device__ __forceinline__ uint32_t smem_u32(const void* p) {
    uint32_t a;
    asm("{ .reg .u64 t; cvta.to.shared.u64 t, %1; cvt.u32.u64 %0, t; }" : "=r"(a) : "l"(p));
    return a;
}

__device__ __forceinline__ void split2(float x0, float x1, uint32_t& hp, uint32_t& lp) {
    asm("cvt.rn.bf16x2.f32 %0, %1, %2;" : "=r"(hp) : "f"(x1), "f"(x0));
    float h0 = __uint_as_float(hp << 16);
    float h1 = __uint_as_float(hp & 0xFFFF0000u);
    float l0 = x0 - h0;
    float l1 = x1 - h1;
    asm("cvt.rn.bf16x2.f32 %0, %1, %2;" : "=r"(lp) : "f"(l1), "f"(l0));
}

__device__ __forceinline__ void ldsm4(uint32_t* r, uint32_t addr) {
    asm volatile("ldmatrix.sync.aligned.m8n8.x4.shared.b16 {%0,%1,%2,%3}, [%4];"
                 : "=r"(r[0]), "=r"(r[1]), "=r"(r[2]), "=r"(r[3]) : "r"(addr));
}

__device__ __forceinline__ void mma_bf16(float* d, const uint32_t* a,
                                         uint32_t b0, uint32_t b1) {
    asm volatile(
        "mma.sync.aligned.m16n8k16.row.col.f32.bf16.bf16.f32 "
        "{%0,%1,%2,%3}, {%4,%5,%6,%7}, {%8,%9}, {%0,%1,%2,%3};"
        : "+f"(d[0]), "+f"(d[1]), "+f"(d[2]), "+f"(d[3])
        : "r"(a[0]), "r"(a[1]), "r"(a[2]), "r"(a[3]), "r"(b0), "r"(b1));
}

// 12 MMAs of one split term; same-acc reuse distance across terms = 12.
#define TERM(AF0, AF1, BF0, BF1)                                   \
    mma_bf16(acc[0][0], AF0, BF0[0], BF0[2]);                      \
    mma_bf16(acc[0][1], AF0, BF0[1], BF0[3]);                      \
    mma_bf16(acc[0][2], AF0, BF1[0], BF1[2]);                      \
    mma_bf16(acc[0][3], AF0, BF1[1], BF1[3]);                      \
    mma_bf16(acc[1][0], AF1, BF0[0], BF0[2]);                      \
    mma_bf16(acc[1][1], AF1, BF0[1], BF0[3]);                      \
    mma_bf16(acc[1][2], AF1, BF1[0], BF1[2]);                      \
    mma_bf16(acc[1][3], AF1, BF1[1], BF1[3]);

__global__ __launch_bounds__(256, 2)
void cv_mma_kernel(const float* __restrict__ L, const float* __restrict__ R,
                   float* __restrict__ out) {
    extern __shared__ char smem[];
    const uint32_t sb = smem_u32(smem);
    const int tid = threadIdx.x;
    const int wid = tid >> 5;
    const int lid = tid & 31;
    const int kt = blockIdx.x;      // 0..4
    const int bh = blockIdx.y;      // 0..1279

    const float* Lg = L + (size_t)bh * WW * CC;
    const float* Rg = R + (size_t)bh * WW * CC;

    // ---- Prologue: split fp32 -> bf16 hi/lo tiles in smem ----
    #pragma unroll
    for (int it = 0; it < 8; it++) {
        int e = tid + it * 256;
        int m = e >> 4, g = e & 15;
        int j = kt * 64 + m;
        if (j > WW - 1) j = WW - 1;         // overrun rows discarded at store
        const float4* src = (const float4*)(Lg + (size_t)j * CC + g * 8);
        float4 v0 = __ldg(src), v1 = __ldg(src + 1);
        uint32_t h0, h1, h2, h3, l0, l1, l2, l3;
        split2(v0.x, v0.y, h0, l0);
        split2(v0.z, v0.w, h1, l1);
        split2(v1.x, v1.y, h2, l2);
        split2(v1.z, v1.w, h3, l3);
        int off = m * ROWB + g * 16;
        *(uint4*)(smem + OFF_AH + off) = make_uint4(h0, h1, h2, h3);
        *(uint4*)(smem + OFF_AL + off) = make_uint4(l0, l1, l2, l3);
    }
    #pragma unroll
    for (int it = 0; it < 4; it++) {
        int e = tid + it * 256;
        int n = e >> 4, g = e & 15;
        int r = kt * 64 + n;
        const float4* src = (const float4*)(Rg + (size_t)r * CC + g * 8);
        float4 v0 = __ldg(src), v1 = __ldg(src + 1);
        uint32_t h0, h1, h2, h3, l0, l1, l2, l3;
        split2(v0.x, v0.y, h0, l0);
        split2(v0.z, v0.w, h1, l1);
        split2(v1.x, v1.y, h2, l2);
        split2(v1.z, v1.w, h3, l3);
        int off = n * ROWB + g * 16;
        *(uint4*)(smem + OFF_BH + off) = make_uint4(h0, h1, h2, h3);
        *(uint4*)(smem + OFF_BL + off) = make_uint4(l0, l1, l2, l3);
    }
    __syncthreads();

    // ---- Warp tiling: 4(M) x 2(N) warps, warp tile 32x32 ----
    const int wm = wid & 3;
    const int wn = wid >> 2;
    const int lrow = lid & 15;
    const int lkb  = (lid >> 4) << 4;
    const uint32_t aH = sb + OFF_AH + (uint32_t)((wm * 32 + lrow) * ROWB + lkb);
    const uint32_t aL = sb + OFF_AL + (uint32_t)((wm * 32 + lrow) * ROWB + lkb);
    const uint32_t bHp = sb + OFF_BH + (uint32_t)((wn * 32 + lrow) * ROWB + lkb);
    const uint32_t bLp = sb + OFF_BL + (uint32_t)((wn * 32 + lrow) * ROWB + lkb);

    float acc[2][4][4];
    #pragma unroll
    for (int mf = 0; mf < 2; mf++)
        #pragma unroll
        for (int nf = 0; nf < 4; nf++)
            #pragma unroll
            for (int c = 0; c < 4; c++) acc[mf][nf][c] = 0.f;

    #pragma unroll
    for (int ks = 0; ks < 8; ks++) {
        // front-batched fragment loads: 8 ldsm4, latencies overlap
        uint32_t fbh0[4], fbh1[4], fbl0[4], fbl1[4];
        uint32_t fah0[4], fah1[4], fal0[4], fal1[4];
        ldsm4(fbh0, bHp + ks * 32);
        ldsm4(fbh1, bHp + 16 * ROWB + ks * 32);
        ldsm4(fbl0, bLp + ks * 32);
        ldsm4(fbl1, bLp + 16 * ROWB + ks * 32);
        ldsm4(fah0, aH + ks * 32);
        ldsm4(fah1, aH + 16 * ROWB + ks * 32);
        ldsm4(fal0, aL + ks * 32);
        ldsm4(fal1, aL + 16 * ROWB + ks * 32);
        // 36 MMAs, term-major: same-acc reuse distance = 8
        TERM(fah0, fah1, fbh0, fbh1)   // Ah*Bh
        TERM(fal0, fal1, fbh0, fbh1)   // Al*Bh
        TERM(fah0, fah1, fbl0, fbl1)   // Ah*Bl
    }
    __syncthreads();

    // ---- Stage into smem [128][65] f32, then coalesced range stores ----
    float* sout = (float*)smem;
    for (int e = tid; e < 128 * 65; e += 256) sout[e] = 0.f;
    __syncthreads();

    const float inv = 1.0f / 128.0f;
    const int mrow = wm * 32 + (lid >> 2);
    const int ncol = wn * 32 + (lid & 3) * 2;
    #pragma unroll
    for (int mf = 0; mf < 2; mf++) {
        #pragma unroll
        for (int nf = 0; nf < 4; nf++) {
            #pragma unroll
            for (int c = 0; c < 4; c++) {
                int m = mrow + mf * 16 + (c >> 1) * 8;
                int n = ncol + nf * 8 + (c & 1);
                int i = m - n;
                if (i >= 0 && i < 64)
                    sout[m * 65 + i] = acc[mf][nf][c] * inv;
            }
        }
    }
    __syncthreads();

    float* og = out + (size_t)bh * WW * DD;
    for (int m2 = wid; m2 < 127; m2 += 8) {
        int j = kt * 64 + m2;
        if (j >= WW) continue;
        int lo2, hi2;
        if (m2 < 64) { lo2 = 0; hi2 = (kt == 0) ? 63 : m2; }  // kt==0: zeros fill i>m2
        else         { lo2 = m2 - 63; hi2 = 63; }
        #pragma unroll
        for (int s = 0; s < 2; s++) {
            int i = lid + 32 * s;
            if (i >= lo2 && i <= hi2)
                og[(size_t)j * DD + i] = sout[m2 * 65 + i];
        }
    }
}

extern "C" void kernel_launch(void* const* d_in, const int* in_sizes, int n_in,
                              void* d_out, int out_size) {
    const float* left  = (const float*)d_in[0];
    const float* right = (const float*)d_in[1];
    float* out = (float*)d_out;

    cudaFuncSetAttribute(cv_mma_kernel,
                         cudaFuncAttributeMaxDynamicSharedMemorySize, SMEM_TOTAL);
    dim3 grid(5, 8 * 160);   // (kt, bh)
    cv_mma_kernel<<<grid, 256, SMEM_TOTAL>>>(left, right, out);
}

// round 6
// speedup vs baseline: 1.0798x; 1.0798x over previous
#include <cuda_runtime.h>
#include <cstdint>

// CostVolume via single tf32 GEMM (mma.sync.m16n8k8.tf32, PTX sm_80+, valid
// under virtual arch compute_103; tcgen05 is sm_103a-only and unavailable).
//
// out[b,h,j,i] = (1/128) * sum_c L[b,h,j,c]*R[b,h,j-i,c], j>=i else 0.
// Per CTA (bh, kt): D[m<128][n<64] = sum_c L[kt*64+m][c]*R[kt*64+n][c];
// out(j=kt*64+m, i=m-n) valid iff 0<=i<64; each out element covered once.
// Accuracy: tf32 (cvt.rna) product error ~2^-11, zero-mean over K=128
// -> aggregate rel err ~4e-4 < 1e-3.
//
// Smem k-permuted layout: element (row, k) stored at row*144 + (k&3)*36 + (k>>2)
// (floats). One LDS.128 per lane at offset (lid&3)*36 + 4t yields the a0/a2
// (resp. b0/b1) fragments for k-steps 2t and 2t+1. Conflict-free: row stride
// 144 = 16 mod 32 banks, block stride 36 = 4 mod 32.

#define WW 320
#define CC 128
#define DD 64
#define RSF 144                          // row stride in floats
#define OFF_A 0
#define OFF_B (128 * RSF * 4)            // 73728
#define SMEM_TOTAL (OFF_B + 64 * RSF * 4) // 110592

__device__ __forceinline__ uint32_t smem_u32(const void* p) {
    uint32_t a;
    asm("{ .reg .u64 t; cvta.to.shared.u64 t, %1; cvt.u32.u64 %0, t; }" : "=r"(a) : "l"(p));
    return a;
}

__device__ __forceinline__ uint32_t f2tf32(float x) {
    uint32_t r;
    asm("cvt.rna.tf32.f32 %0, %1;" : "=r"(r) : "f"(x));
    return r;
}

__device__ __forceinline__ uint4 lds128(uint32_t addr) {
    uint4 v;
    asm("ld.shared.v4.b32 {%0,%1,%2,%3}, [%4];"
        : "=r"(v.x), "=r"(v.y), "=r"(v.z), "=r"(v.w) : "r"(addr));
    return v;
}

__device__ __forceinline__ void mma_tf32(float* d, uint32_t a0, uint32_t a1,
                                         uint32_t a2, uint32_t a3,
                                         uint32_t b0, uint32_t b1) {
    asm volatile(
        "mma.sync.aligned.m16n8k8.row.col.f32.tf32.tf32.f32 "
        "{%0,%1,%2,%3}, {%4,%5,%6,%7}, {%8,%9}, {%0,%1,%2,%3};"
        : "+f"(d[0]), "+f"(d[1]), "+f"(d[2]), "+f"(d[3])
        : "r"(a0), "r"(a1), "r"(a2), "r"(a3), "r"(b0), "r"(b1));
}

__global__ __launch_bounds__(256, 2)
void cv_tf32_kernel(const float* __restrict__ L, const float* __restrict__ R,
                    float* __restrict__ out) {
    extern __shared__ char smem[];
    const uint32_t sb = smem_u32(smem);
    const int tid = threadIdx.x;
    const int wid = tid >> 5;
    const int lid = tid & 31;
    const int kt = blockIdx.x;      // 0..4
    const int bh = blockIdx.y;      // 0..1279

    const float* Lg = L + (size_t)bh * WW * CC;
    const float* Rg = R + (size_t)bh * WW * CC;

    uint32_t* sA = (uint32_t*)(smem + OFF_A);
    uint32_t* sB = (uint32_t*)(smem + OFF_B);

    // ---- Prologue: LDG.128, cvt.rna.tf32, permuted STS.32 ----
    // A: L rows kt*64 .. kt*64+127 (clamped; overrun rows discarded at store)
    #pragma unroll
    for (int it = 0; it < 16; it++) {
        int e = tid + it * 256;
        int m = e >> 5, g = e & 31;          // row m, float4-granule g
        int j = kt * 64 + m;
        if (j > WW - 1) j = WW - 1;
        float4 v = __ldg((const float4*)(Lg + (size_t)j * CC + g * 4));
        uint32_t* dst = sA + m * RSF + g;
        dst[0]   = f2tf32(v.x);
        dst[36]  = f2tf32(v.y);
        dst[72]  = f2tf32(v.z);
        dst[108] = f2tf32(v.w);
    }
    // B: R rows kt*64 .. kt*64+63 (always in range)
    #pragma unroll
    for (int it = 0; it < 8; it++) {
        int e = tid + it * 256;
        int n = e >> 5, g = e & 31;
        int r = kt * 64 + n;
        float4 v = __ldg((const float4*)(Rg + (size_t)r * CC + g * 4));
        uint32_t* dst = sB + n * RSF + g;
        dst[0]   = f2tf32(v.x);
        dst[36]  = f2tf32(v.y);
        dst[72]  = f2tf32(v.z);
        dst[108] = f2tf32(v.w);
    }
    __syncthreads();

    // ---- Warp tiling: 4(M) x 2(N) warps, warp tile 32x32 ----
    const int wm = wid & 3;
    const int wn = wid >> 2;
    const int lr = lid >> 2;      // group id
    const int lc = lid & 3;       // k id within group
    const uint32_t aBase = sb + OFF_A + (uint32_t)(((wm * 32 + lr) * RSF + lc * 36) * 4);
    const uint32_t bBase = sb + OFF_B + (uint32_t)(((wn * 32 + lr) * RSF + lc * 36) * 4);
    const uint32_t R8 = 8 * RSF * 4;   // 8-row stride in bytes

    float acc[2][4][4];
    #pragma unroll
    for (int mf = 0; mf < 2; mf++)
        #pragma unroll
        for (int nf = 0; nf < 4; nf++)
            #pragma unroll
            for (int c = 0; c < 4; c++) acc[mf][nf][c] = 0.f;

    #pragma unroll
    for (int t = 0; t < 8; t++) {     // each t covers k-steps 2t, 2t+1 (16 k's)
        const uint32_t ko = t * 16;
        uint4 a0 = lds128(aBase + ko);            // rows lr, for mf0 groups
        uint4 a1 = lds128(aBase + R8 + ko);       // +8
        uint4 a2 = lds128(aBase + 2 * R8 + ko);   // +16 (mf1)
        uint4 a3 = lds128(aBase + 3 * R8 + ko);   // +24
        uint4 b0 = lds128(bBase + ko);            // n-block 0
        uint4 b1 = lds128(bBase + R8 + ko);       // n-block 1
        uint4 b2 = lds128(bBase + 2 * R8 + ko);
        uint4 b3 = lds128(bBase + 3 * R8 + ko);
        // k-step 2t: lanes use .x (k) / .y (k+4)
        mma_tf32(acc[0][0], a0.x, a1.x, a0.y, a1.y, b0.x, b0.y);
        mma_tf32(acc[0][1], a0.x, a1.x, a0.y, a1.y, b1.x, b1.y);
        mma_tf32(acc[0][2], a0.x, a1.x, a0.y, a1.y, b2.x, b2.y);
        mma_tf32(acc[0][3], a0.x, a1.x, a0.y, a1.y, b3.x, b3.y);
        mma_tf32(acc[1][0], a2.x, a3.x, a2.y, a3.y, b0.x, b0.y);
        mma_tf32(acc[1][1], a2.x, a3.x, a2.y, a3.y, b1.x, b1.y);
        mma_tf32(acc[1][2], a2.x, a3.x, a2.y, a3.y, b2.x, b2.y);
        mma_tf32(acc[1][3], a2.x, a3.x, a2.y, a3.y, b3.x, b3.y);
        // k-step 2t+1: .z / .w
        mma_tf32(acc[0][0], a0.z, a1.z, a0.w, a1.w, b0.z, b0.w);
        mma_tf32(acc[0][1], a0.z, a1.z, a0.w, a1.w, b1.z, b1.w);
        mma_tf32(acc[0][2], a0.z, a1.z, a0.w, a1.w, b2.z, b2.w);
        mma_tf32(acc[0][3], a0.z, a1.z, a0.w, a1.w, b3.z, b3.w);
        mma_tf32(acc[1][0], a2.z, a3.z, a2.w, a3.w, b0.z, b0.w);
        mma_tf32(acc[1][1], a2.z, a3.z, a2.w, a3.w, b1.z, b1.w);
        mma_tf32(acc[1][2], a2.z, a3.z, a2.w, a3.w, b2.z, b2.w);
        mma_tf32(acc[1][3], a2.z, a3.z, a2.w, a3.w, b3.z, b3.w);
    }
    __syncthreads();

    // ---- Stage into smem [128][65] f32, then coalesced range stores ----
    float* sout = (float*)smem;
    for (int e = tid; e < 128 * 65; e += 256) sout[e] = 0.f;
    __syncthreads();

    const float inv = 1.0f / 128.0f;
    const int mrow = wm * 32 + lr;
    const int ncol = wn * 32 + lc * 2;
    #pragma unroll
    for (int mf = 0; mf < 2; mf++) {
        #pragma unroll
        for (int nf = 0; nf < 4; nf++) {
            #pragma unroll
            for (int c = 0; c < 4; c++) {
                int m = mrow + mf * 16 + (c >> 1) * 8;
                int n = ncol + nf * 8 + (c & 1);
                int i = m - n;
                if (i >= 0 && i < 64)
                    sout[m * 65 + i] = acc[mf][nf][c] * inv;
            }
        }
    }
    __syncthreads();

    float* og = out + (size_t)bh * WW * DD;
    for (int m2 = wid; m2 < 127; m2 += 8) {
        int j = kt * 64 + m2;
        if (j >= WW) continue;
        int lo2, hi2;
        if (m2 < 64) { lo2 = 0; hi2 = (kt == 0) ? 63 : m2; }  // kt==0: zeros fill i>m2
        else         { lo2 = m2 - 63; hi2 = 63; }
        #pragma unroll
        for (int s = 0; s < 2; s++) {
            int i = lid + 32 * s;
            if (i >= lo2 && i <= hi2)
                og[(size_t)j * DD + i] = sout[m2 * 65 + i];
        }
    }
}

extern "C" void kernel_launch(void* const* d_in, const int* in_sizes, int n_in,
                              void* d_out, int out_size) {
    const float* left  = (const float*)d_in[0];
    const float* right = (const float*)d_in[1];
    float* out = (float*)d_out;

    cudaFuncSetAttribute(cv_tf32_kernel,
                         cudaFuncAttributeMaxDynamicSharedMemorySize, SMEM_TOTAL);
    dim3 grid(5, 8 * 160);   // (kt, bh)
    cv_tf32_kernel<<<grid, 256, SMEM_TOTAL>>>(left, right, out);
}

// round 7
// speedup vs baseline: 1.2298x; 1.1389x over previous
#include <cuda_runtime.h>
#include <cstdint>

// CostVolume via single tf32 GEMM (mma.sync.m16n8k8.tf32; tcgen05 unavailable
// under virtual arch compute_103).
//
// out[b,h,j,i] = (1/128) * sum_c L[b,h,j,c]*R[b,h,j-i,c], j>=i else 0.
// Per CTA (bh, kt): D[m<128][n<64] = sum_c L[kt*64+m][c]*R[kt*64+n][c];
// out(j=kt*64+m, i=m-n) valid iff 0<=i<64; covered exactly once (row m=127
// never valid). kt==0 CTAs also write the j<i zeros (n<0 region).
//
// Smem k-permute: (row,k) at row*144 + (k&3)*36 + (k>>2) floats; one LDS.128
// at lc*36 + 4t yields fragments for k-steps 2t,2t+1. Conflict-free.

#define WW 320
#define CC 128
#define DD 64
#define RSF 144
#define OFF_A 0
#define OFF_B (128 * RSF * 4)
#define SMEM_TOTAL (OFF_B + 64 * RSF * 4)   // 110592

__device__ __forceinline__ uint32_t smem_u32(const void* p) {
    uint32_t a;
    asm("{ .reg .u64 t; cvta.to.shared.u64 t, %1; cvt.u32.u64 %0, t; }" : "=r"(a) : "l"(p));
    return a;
}
__device__ __forceinline__ uint32_t f2tf32(float x) {
    uint32_t r;
    asm("cvt.rna.tf32.f32 %0, %1;" : "=r"(r) : "f"(x));
    return r;
}
__device__ __forceinline__ uint4 lds128(uint32_t addr) {
    uint4 v;
    asm("ld.shared.v4.b32 {%0,%1,%2,%3}, [%4];"
        : "=r"(v.x), "=r"(v.y), "=r"(v.z), "=r"(v.w) : "r"(addr));
    return v;
}
__device__ __forceinline__ void mma_tf32(float* d, uint32_t a0, uint32_t a1,
                                         uint32_t a2, uint32_t a3,
                                         uint32_t b0, uint32_t b1) {
    asm volatile(
        "mma.sync.aligned.m16n8k8.row.col.f32.tf32.tf32.f32 "
        "{%0,%1,%2,%3}, {%4,%5,%6,%7}, {%8,%9}, {%0,%1,%2,%3};"
        : "+f"(d[0]), "+f"(d[1]), "+f"(d[2]), "+f"(d[3])
        : "r"(a0), "r"(a1), "r"(a2), "r"(a3), "r"(b0), "r"(b1));
}

__global__ __launch_bounds__(256, 2)
void cv_tf32_kernel(const float* __restrict__ L, const float* __restrict__ R,
                    float* __restrict__ out) {
    extern __shared__ char smem[];
    const uint32_t sb = smem_u32(smem);
    const int tid = threadIdx.x;
    const int wid = tid >> 5;
    const int lid = tid & 31;
    const int kt = blockIdx.x;      // 0..4
    const int bh = blockIdx.y;      // 0..1279

    const float* Lg = L + (size_t)bh * WW * CC;
    const float* Rg = R + (size_t)bh * WW * CC;

    // ---- Prologue: pointer-marched LDG.128 -> cvt.rna -> permuted STS.32 ----
    {
        const int g  = tid & 31;        // float4 granule (k = 4g..4g+3)
        const int m0 = tid >> 5;        // starting row, stride 8
        // A: rows kt*64 + m (clamped to 319; overrun rows pruned at store)
        int jbase = kt * 64 + m0;
        const float4* srcA = (const float4*)(Lg + (size_t)min(jbase, WW - 1) * CC) + g;
        uint32_t* dstA = (uint32_t*)(smem + OFF_A) + m0 * RSF + g;
        #pragma unroll
        for (int it = 0; it < 16; it++) {
            float4 v = __ldg(srcA);
            dstA[0]   = f2tf32(v.x);
            dstA[36]  = f2tf32(v.y);
            dstA[72]  = f2tf32(v.z);
            dstA[108] = f2tf32(v.w);
            int jn = jbase + (it + 1) * 8;
            srcA = (const float4*)(Lg + (size_t)min(jn, WW - 1) * CC) + g;
            dstA += 8 * RSF;
        }
        // B: rows kt*64 + n, always in range
        const float4* srcB = (const float4*)(Rg + (size_t)(kt * 64 + m0) * CC) + g;
        uint32_t* dstB = (uint32_t*)(smem + OFF_B) + m0 * RSF + g;
        #pragma unroll
        for (int it = 0; it < 8; it++) {
            float4 v = __ldg(srcB);
            dstB[0]   = f2tf32(v.x);
            dstB[36]  = f2tf32(v.y);
            dstB[72]  = f2tf32(v.z);
            dstB[108] = f2tf32(v.w);
            srcB += 8 * (CC / 4);
            dstB += 8 * RSF;
        }
    }
    __syncthreads();

    // ---- Mainloop: 4(M) x 2(N) warps, warp tile 32x32 ----
    const int wm = wid & 3;
    const int wn = wid >> 2;
    const int lr = lid >> 2;
    const int lc = lid & 3;
    const uint32_t aBase = sb + OFF_A + (uint32_t)(((wm * 32 + lr) * RSF + lc * 36) * 4);
    const uint32_t bBase = sb + OFF_B + (uint32_t)(((wn * 32 + lr) * RSF + lc * 36) * 4);
    const uint32_t R8 = 8 * RSF * 4;

    float acc[2][4][4];
    #pragma unroll
    for (int mf = 0; mf < 2; mf++)
        #pragma unroll
        for (int nf = 0; nf < 4; nf++)
            #pragma unroll
            for (int c = 0; c < 4; c++) acc[mf][nf][c] = 0.f;

    #pragma unroll
    for (int t = 0; t < 8; t++) {
        const uint32_t ko = t * 16;
        uint4 a0 = lds128(aBase + ko);
        uint4 a1 = lds128(aBase + R8 + ko);
        uint4 a2 = lds128(aBase + 2 * R8 + ko);
        uint4 a3 = lds128(aBase + 3 * R8 + ko);
        uint4 b0 = lds128(bBase + ko);
        uint4 b1 = lds128(bBase + R8 + ko);
        uint4 b2 = lds128(bBase + 2 * R8 + ko);
        uint4 b3 = lds128(bBase + 3 * R8 + ko);
        mma_tf32(acc[0][0], a0.x, a1.x, a0.y, a1.y, b0.x, b0.y);
        mma_tf32(acc[0][1], a0.x, a1.x, a0.y, a1.y, b1.x, b1.y);
        mma_tf32(acc[0][2], a0.x, a1.x, a0.y, a1.y, b2.x, b2.y);
        mma_tf32(acc[0][3], a0.x, a1.x, a0.y, a1.y, b3.x, b3.y);
        mma_tf32(acc[1][0], a2.x, a3.x, a2.y, a3.y, b0.x, b0.y);
        mma_tf32(acc[1][1], a2.x, a3.x, a2.y, a3.y, b1.x, b1.y);
        mma_tf32(acc[1][2], a2.x, a3.x, a2.y, a3.y, b2.x, b2.y);
        mma_tf32(acc[1][3], a2.x, a3.x, a2.y, a3.y, b3.x, b3.y);
        mma_tf32(acc[0][0], a0.z, a1.z, a0.w, a1.w, b0.z, b0.w);
        mma_tf32(acc[0][1], a0.z, a1.z, a0.w, a1.w, b1.z, b1.w);
        mma_tf32(acc[0][2], a0.z, a1.z, a0.w, a1.w, b2.z, b2.w);
        mma_tf32(acc[0][3], a0.z, a1.z, a0.w, a1.w, b3.z, b3.w);
        mma_tf32(acc[1][0], a2.z, a3.z, a2.w, a3.w, b0.z, b0.w);
        mma_tf32(acc[1][1], a2.z, a3.z, a2.w, a3.w, b1.z, b1.w);
        mma_tf32(acc[1][2], a2.z, a3.z, a2.w, a3.w, b2.z, b2.w);
        mma_tf32(acc[1][3], a2.z, a3.z, a2.w, a3.w, b3.z, b3.w);
    }

    // ---- Epilogue: direct predicated stores (L2 merges spans into lines) ----
    const float inv = 1.0f / 128.0f;
    float* og = out + (size_t)bh * WW * DD;
    const int mrow = wm * 32 + lr;
    const int ncol = wn * 32 + lc * 2;
    const int jrow = kt * 64 + mrow;
    #pragma unroll
    for (int mf = 0; mf < 2; mf++) {
        #pragma unroll
        for (int c2 = 0; c2 < 2; c2++) {          // c>>1: +0/+8 m rows
            int j = jrow + mf * 16 + c2 * 8;
            if (j >= WW) continue;                 // kt==4 overrun rows
            int m = j - kt * 64;
            float* orow = og + (size_t)j * DD;
            #pragma unroll
            for (int nf = 0; nf < 4; nf++) {
                #pragma unroll
                for (int c1 = 0; c1 < 2; c1++) {   // c&1: n parity
                    int n = ncol + nf * 8 + c1;
                    int i = m - n;
                    if (i >= 0 && i < 64)
                        orow[i] = acc[mf][nf][c2 * 2 + c1] * inv;
                }
            }
        }
    }
    // kt==0: zeros for j<i (n<0 region, untouched by any GEMM tile)
    if (kt == 0) {
        #pragma unroll
        for (int e = tid; e < 64 * 64; e += 256) {
            int j = e >> 6, i = e & 63;
            if (i > j) og[(size_t)j * DD + i] = 0.f;
        }
    }
}

extern "C" void kernel_launch(void* const* d_in, const int* in_sizes, int n_in,
                              void* d_out, int out_size) {
    const float* left  = (const float*)d_in[0];
    const float* right = (const float*)d_in[1];
    float* out = (float*)d_out;

    cudaFuncSetAttribute(cv_tf32_kernel,
                         cudaFuncAttributeMaxDynamicSharedMemorySize, SMEM_TOTAL);
    dim3 grid(5, 8 * 160);   // (kt, bh)
    cv_tf32_kernel<<<grid, 256, SMEM_TOTAL>>>(left, right, out);
}

// round 9
// speedup vs baseline: 1.4904x; 1.2119x over previous
#include <cuda_runtime.h>
#include <cstdint>

// CostVolume via single tf32 GEMM (mma.sync.m16n8k8.tf32; tcgen05 unavailable
// under virtual arch compute_103).
//
// out[b,h,j,i] = (1/128) * sum_c L[b,h,j,c]*R[b,h,j-i,c], j>=i else 0.
// Per CTA (bh, kt): D[m<128][n<64] = sum_c L[kt*64+m][c]*R[kt*64+n][c];
// out(j=kt*64+m, i=m-n) valid iff 0<=i<64; covered exactly once.
// kt==0 CTAs also write the j<i zeros.
//
// K processed in 2 sequential halves of 64 reusing one smem buffer:
// smem/CTA = 60KB -> 3 CTAs/SM. Half-K permuted layout: (row, k') at
// row*80 + (k'&3)*20 + (k'>>2) floats; one LDS.128 at lc*20 + 4t yields
// fragments for k-steps 2t,2t+1. Conflict-free.
//
// NOTE: lds128 MUST be asm volatile + memory clobber — the two K-halves
// load from identical smem addresses and a non-volatile asm gets CSE'd
// across the barrier (round-8 bug: second half reused first-half data).

#define WW 320
#define CC 128
#define DD 64
#define RSF 80                      // row stride in floats (half-K)
#define OFF_A 0
#define OFF_B (128 * RSF * 4)       // 40960
#define SMEM_TOTAL (OFF_B + 64 * RSF * 4)   // 61440

__device__ __forceinline__ uint32_t smem_u32(const void* p) {
    uint32_t a;
    asm("{ .reg .u64 t; cvta.to.shared.u64 t, %1; cvt.u32.u64 %0, t; }" : "=r"(a) : "l"(p));
    return a;
}
__device__ __forceinline__ uint32_t f2tf32(float x) {
    uint32_t r;
    asm("cvt.rna.tf32.f32 %0, %1;" : "=r"(r) : "f"(x));
    return r;
}
__device__ __forceinline__ uint4 lds128(uint32_t addr) {
    uint4 v;
    asm volatile("ld.shared.v4.b32 {%0,%1,%2,%3}, [%4];"
                 : "=r"(v.x), "=r"(v.y), "=r"(v.z), "=r"(v.w)
                 : "r"(addr) : "memory");
    return v;
}
__device__ __forceinline__ void mma_tf32(float* d, uint32_t a0, uint32_t a1,
                                         uint32_t a2, uint32_t a3,
                                         uint32_t b0, uint32_t b1) {
    asm volatile(
        "mma.sync.aligned.m16n8k8.row.col.f32.tf32.tf32.f32 "
        "{%0,%1,%2,%3}, {%4,%5,%6,%7}, {%8,%9}, {%0,%1,%2,%3};"
        : "+f"(d[0]), "+f"(d[1]), "+f"(d[2]), "+f"(d[3])
        : "r"(a0), "r"(a1), "r"(a2), "r"(a3), "r"(b0), "r"(b1));
}

__global__ __launch_bounds__(256, 3)
void cv_tf32_kernel(const float* __restrict__ L, const float* __restrict__ R,
                    float* __restrict__ out) {
    extern __shared__ char smem[];
    const uint32_t sb = smem_u32(smem);
    const int tid = threadIdx.x;
    const int wid = tid >> 5;
    const int lid = tid & 31;
    const int kt = blockIdx.x;      // 0..4
    const int bh = blockIdx.y;      // 0..1279

    const float* Lg = L + (size_t)bh * WW * CC;
    const float* Rg = R + (size_t)bh * WW * CC;

    const int wm = wid & 3;
    const int wn = wid >> 2;
    const int lr = lid >> 2;
    const int lc = lid & 3;
    const uint32_t aBase = sb + OFF_A + (uint32_t)(((wm * 32 + lr) * RSF + lc * 20) * 4);
    const uint32_t bBase = sb + OFF_B + (uint32_t)(((wn * 32 + lr) * RSF + lc * 20) * 4);
    const uint32_t R8 = 8 * RSF * 4;

    const int g  = tid & 15;        // granule: k' = 4g..4g+3
    const int m0 = tid >> 4;        // starting row, stride 16

    float acc[2][4][4];
    #pragma unroll
    for (int mf = 0; mf < 2; mf++)
        #pragma unroll
        for (int nf = 0; nf < 4; nf++)
            #pragma unroll
            for (int c = 0; c < 4; c++) acc[mf][nf][c] = 0.f;

    #pragma unroll
    for (int kh = 0; kh < 2; kh++) {
        if (kh) __syncthreads();    // drain readers before overwriting smem

        // ---- Prologue: LDG.128 -> cvt.rna -> permuted STS.32 (half-K) ----
        {
            const int csrc = kh * 64 + g * 4;
            uint32_t* dstA = (uint32_t*)(smem + OFF_A) + m0 * RSF + g;
            #pragma unroll
            for (int it = 0; it < 8; it++) {
                int j = kt * 64 + m0 + it * 16;
                if (j > WW - 1) j = WW - 1;     // overrun rows pruned at store
                float4 v = __ldg((const float4*)(Lg + (size_t)j * CC + csrc));
                dstA[0]  = f2tf32(v.x);
                dstA[20] = f2tf32(v.y);
                dstA[40] = f2tf32(v.z);
                dstA[60] = f2tf32(v.w);
                dstA += 16 * RSF;
            }
            uint32_t* dstB = (uint32_t*)(smem + OFF_B) + m0 * RSF + g;
            const float4* srcB = (const float4*)(Rg + (size_t)(kt * 64 + m0) * CC + csrc);
            #pragma unroll
            for (int it = 0; it < 4; it++) {
                float4 v = __ldg(srcB);
                dstB[0]  = f2tf32(v.x);
                dstB[20] = f2tf32(v.y);
                dstB[40] = f2tf32(v.z);
                dstB[60] = f2tf32(v.w);
                srcB += 16 * (CC / 4);
                dstB += 16 * RSF;
            }
        }
        __syncthreads();

        // ---- Mainloop: 4(M) x 2(N) warps, warp tile 32x32, 4 t-iters ----
        #pragma unroll
        for (int t = 0; t < 4; t++) {
            const uint32_t ko = t * 16;
            uint4 a0 = lds128(aBase + ko);
            uint4 a1 = lds128(aBase + R8 + ko);
            uint4 a2 = lds128(aBase + 2 * R8 + ko);
            uint4 a3 = lds128(aBase + 3 * R8 + ko);
            uint4 b0 = lds128(bBase + ko);
            uint4 b1 = lds128(bBase + R8 + ko);
            uint4 b2 = lds128(bBase + 2 * R8 + ko);
            uint4 b3 = lds128(bBase + 3 * R8 + ko);
            mma_tf32(acc[0][0], a0.x, a1.x, a0.y, a1.y, b0.x, b0.y);
            mma_tf32(acc[0][1], a0.x, a1.x, a0.y, a1.y, b1.x, b1.y);
            mma_tf32(acc[0][2], a0.x, a1.x, a0.y, a1.y, b2.x, b2.y);
            mma_tf32(acc[0][3], a0.x, a1.x, a0.y, a1.y, b3.x, b3.y);
            mma_tf32(acc[1][0], a2.x, a3.x, a2.y, a3.y, b0.x, b0.y);
            mma_tf32(acc[1][1], a2.x, a3.x, a2.y, a3.y, b1.x, b1.y);
            mma_tf32(acc[1][2], a2.x, a3.x, a2.y, a3.y, b2.x, b2.y);
            mma_tf32(acc[1][3], a2.x, a3.x, a2.y, a3.y, b3.x, b3.y);
            mma_tf32(acc[0][0], a0.z, a1.z, a0.w, a1.w, b0.z, b0.w);
            mma_tf32(acc[0][1], a0.z, a1.z, a0.w, a1.w, b1.z, b1.w);
            mma_tf32(acc[0][2], a0.z, a1.z, a0.w, a1.w, b2.z, b2.w);
            mma_tf32(acc[0][3], a0.z, a1.z, a0.w, a1.w, b3.z, b3.w);
            mma_tf32(acc[1][0], a2.z, a3.z, a2.w, a3.w, b0.z, b0.w);
            mma_tf32(acc[1][1], a2.z, a3.z, a2.w, a3.w, b1.z, b1.w);
            mma_tf32(acc[1][2], a2.z, a3.z, a2.w, a3.w, b2.z, b2.w);
            mma_tf32(acc[1][3], a2.z, a3.z, a2.w, a3.w, b3.z, b3.w);
        }
    }

    // ---- Epilogue: direct predicated stores (L2 merges spans) ----
    const float inv = 1.0f / 128.0f;
    float* og = out + (size_t)bh * WW * DD;
    const int mrow = wm * 32 + lr;
    const int ncol = wn * 32 + lc * 2;
    const int jrow = kt * 64 + mrow;
    #pragma unroll
    for (int mf = 0; mf < 2; mf++) {
        #pragma unroll
        for (int c2 = 0; c2 < 2; c2++) {
            int j = jrow + mf * 16 + c2 * 8;
            if (j >= WW) continue;
            int m = j - kt * 64;
            float* orow = og + (size_t)j * DD;
            #pragma unroll
            for (int nf = 0; nf < 4; nf++) {
                #pragma unroll
                for (int c1 = 0; c1 < 2; c1++) {
                    int n = ncol + nf * 8 + c1;
                    int i = m - n;
                    if (i >= 0 && i < 64)
                        orow[i] = acc[mf][nf][c2 * 2 + c1] * inv;
                }
            }
        }
    }
    if (kt == 0) {      // zeros for j<i (n<0 region)
        #pragma unroll
        for (int e = tid; e < 64 * 64; e += 256) {
            int j = e >> 6, i = e & 63;
            if (i > j) og[(size_t)j * DD + i] = 0.f;
        }
    }
}

extern "C" void kernel_launch(void* const* d_in, const int* in_sizes, int n_in,
                              void* d_out, int out_size) {
    const float* left  = (const float*)d_in[0];
    const float* right = (const float*)d_in[1];
    float* out = (float*)d_out;

    cudaFuncSetAttribute(cv_tf32_kernel,
                         cudaFuncAttributeMaxDynamicSharedMemorySize, SMEM_TOTAL);
    dim3 grid(5, 8 * 160);   // (kt, bh)
    cv_tf32_kernel<<<grid, 256, SMEM_TOTAL>>>(left, right, out);
}

// round 10
// speedup vs baseline: 1.5379x; 1.0319x over previous
#include <cuda_runtime.h>
#include <cstdint>

// CostVolume via single tf32 GEMM (mma.sync.m16n8k8.tf32; tcgen05 unavailable
// under virtual arch compute_103).
//
// out[b,h,j,i] = (1/128) * sum_c L[b,h,j,c]*R[b,h,j-i,c], j>=i else 0.
// Per CTA (bh, kt): D[m<128][n<64] = sum_c L[kt*64+m][c]*R[kt*64+n][c];
// out(j=kt*64+m, i=m-n) valid iff 0<=i<64; covered exactly once.
//
// Dead-warp skip: warps (wm,wn)=(3,0) [i>=65] and (0,1) [i<0] (wid 3,4)
// produce no valid outputs -> they skip mainloop+epilogue (-25% MMA/LDS)
// and instead handle the kt==0 j<i zero region concurrently.
//
// K processed in 2 sequential halves of 64 reusing one smem buffer
// (60KB/CTA -> 3 CTAs/SM). Half-K permuted layout: (row,k') at
// row*80 + (k'&3)*20 + (k'>>2) floats; LDS.128 at lc*20+4t gives fragments
// for k-steps 2t,2t+1; conflict-free. lds128 MUST be volatile+memory-clobber
// (identical addresses across the two halves; CSE across barriers otherwise).

#define WW 320
#define CC 128
#define DD 64
#define RSF 80
#define OFF_A 0
#define OFF_B (128 * RSF * 4)
#define SMEM_TOTAL (OFF_B + 64 * RSF * 4)   // 61440

__device__ __forceinline__ uint32_t smem_u32(const void* p) {
    uint32_t a;
    asm("{ .reg .u64 t; cvta.to.shared.u64 t, %1; cvt.u32.u64 %0, t; }" : "=r"(a) : "l"(p));
    return a;
}
__device__ __forceinline__ uint32_t f2tf32(float x) {
    uint32_t r;
    asm("cvt.rna.tf32.f32 %0, %1;" : "=r"(r) : "f"(x));
    return r;
}
__device__ __forceinline__ uint4 lds128(uint32_t addr) {
    uint4 v;
    asm volatile("ld.shared.v4.b32 {%0,%1,%2,%3}, [%4];"
                 : "=r"(v.x), "=r"(v.y), "=r"(v.z), "=r"(v.w)
                 : "r"(addr) : "memory");
    return v;
}
__device__ __forceinline__ void mma_tf32(float* d, uint32_t a0, uint32_t a1,
                                         uint32_t a2, uint32_t a3,
                                         uint32_t b0, uint32_t b1) {
    asm volatile(
        "mma.sync.aligned.m16n8k8.row.col.f32.tf32.tf32.f32 "
        "{%0,%1,%2,%3}, {%4,%5,%6,%7}, {%8,%9}, {%0,%1,%2,%3};"
        : "+f"(d[0]), "+f"(d[1]), "+f"(d[2]), "+f"(d[3])
        : "r"(a0), "r"(a1), "r"(a2), "r"(a3), "r"(b0), "r"(b1));
}

__global__ __launch_bounds__(256, 3)
void cv_tf32_kernel(const float* __restrict__ L, const float* __restrict__ R,
                    float* __restrict__ out) {
    extern __shared__ char smem[];
    const uint32_t sb = smem_u32(smem);
    const int tid = threadIdx.x;
    const int wid = tid >> 5;
    const int lid = tid & 31;
    const int kt = blockIdx.x;      // 0..4
    const int bh = blockIdx.y;      // 0..1279

    const float* Lg = L + (size_t)bh * WW * CC;
    const float* Rg = R + (size_t)bh * WW * CC;
    float* og = out + (size_t)bh * WW * DD;

    const int wm = wid & 3;
    const int wn = wid >> 2;
    const bool work = (wid != 3) && (wid != 4);   // band-dead warps: (3,0),(0,1)
    const int lr = lid >> 2;
    const int lc = lid & 3;
    const uint32_t aBase = sb + OFF_A + (uint32_t)(((wm * 32 + lr) * RSF + lc * 20) * 4);
    const uint32_t bBase = sb + OFF_B + (uint32_t)(((wn * 32 + lr) * RSF + lc * 20) * 4);
    const uint32_t R8 = 8 * RSF * 4;

    const int g  = tid & 15;        // granule: k' = 4g..4g+3
    const int m0 = tid >> 4;        // starting row, stride 16

    float acc[2][4][4];
    #pragma unroll
    for (int mf = 0; mf < 2; mf++)
        #pragma unroll
        for (int nf = 0; nf < 4; nf++)
            #pragma unroll
            for (int c = 0; c < 4; c++) acc[mf][nf][c] = 0.f;

    #pragma unroll
    for (int kh = 0; kh < 2; kh++) {
        if (kh) __syncthreads();    // drain readers before overwriting smem

        // ---- Prologue (all threads): LDG.128 -> cvt.rna -> permuted STS ----
        {
            const int csrc = kh * 64 + g * 4;
            uint32_t* dstA = (uint32_t*)(smem + OFF_A) + m0 * RSF + g;
            #pragma unroll
            for (int it = 0; it < 8; it++) {
                int j = kt * 64 + m0 + it * 16;
                if (j > WW - 1) j = WW - 1;     // overrun rows pruned at store
                float4 v = __ldg((const float4*)(Lg + (size_t)j * CC + csrc));
                dstA[0]  = f2tf32(v.x);
                dstA[20] = f2tf32(v.y);
                dstA[40] = f2tf32(v.z);
                dstA[60] = f2tf32(v.w);
                dstA += 16 * RSF;
            }
            uint32_t* dstB = (uint32_t*)(smem + OFF_B) + m0 * RSF + g;
            const float4* srcB = (const float4*)(Rg + (size_t)(kt * 64 + m0) * CC + csrc);
            #pragma unroll
            for (int it = 0; it < 4; it++) {
                float4 v = __ldg(srcB);
                dstB[0]  = f2tf32(v.x);
                dstB[20] = f2tf32(v.y);
                dstB[40] = f2tf32(v.z);
                dstB[60] = f2tf32(v.w);
                srcB += 16 * (CC / 4);
                dstB += 16 * RSF;
            }
        }
        __syncthreads();

        if (work) {
            // ---- Mainloop: warp tile 32x32, 4 t-iters per half ----
            #pragma unroll
            for (int t = 0; t < 4; t++) {
                const uint32_t ko = t * 16;
                uint4 a0 = lds128(aBase + ko);
                uint4 a1 = lds128(aBase + R8 + ko);
                uint4 a2 = lds128(aBase + 2 * R8 + ko);
                uint4 a3 = lds128(aBase + 3 * R8 + ko);
                uint4 b0 = lds128(bBase + ko);
                uint4 b1 = lds128(bBase + R8 + ko);
                uint4 b2 = lds128(bBase + 2 * R8 + ko);
                uint4 b3 = lds128(bBase + 3 * R8 + ko);
                mma_tf32(acc[0][0], a0.x, a1.x, a0.y, a1.y, b0.x, b0.y);
                mma_tf32(acc[0][1], a0.x, a1.x, a0.y, a1.y, b1.x, b1.y);
                mma_tf32(acc[0][2], a0.x, a1.x, a0.y, a1.y, b2.x, b2.y);
                mma_tf32(acc[0][3], a0.x, a1.x, a0.y, a1.y, b3.x, b3.y);
                mma_tf32(acc[1][0], a2.x, a3.x, a2.y, a3.y, b0.x, b0.y);
                mma_tf32(acc[1][1], a2.x, a3.x, a2.y, a3.y, b1.x, b1.y);
                mma_tf32(acc[1][2], a2.x, a3.x, a2.y, a3.y, b2.x, b2.y);
                mma_tf32(acc[1][3], a2.x, a3.x, a2.y, a3.y, b3.x, b3.y);
                mma_tf32(acc[0][0], a0.z, a1.z, a0.w, a1.w, b0.z, b0.w);
                mma_tf32(acc[0][1], a0.z, a1.z, a0.w, a1.w, b1.z, b1.w);
                mma_tf32(acc[0][2], a0.z, a1.z, a0.w, a1.w, b2.z, b2.w);
                mma_tf32(acc[0][3], a0.z, a1.z, a0.w, a1.w, b3.z, b3.w);
                mma_tf32(acc[1][0], a2.z, a3.z, a2.w, a3.w, b0.z, b0.w);
                mma_tf32(acc[1][1], a2.z, a3.z, a2.w, a3.w, b1.z, b1.w);
                mma_tf32(acc[1][2], a2.z, a3.z, a2.w, a3.w, b2.z, b2.w);
                mma_tf32(acc[1][3], a2.z, a3.z, a2.w, a3.w, b3.z, b3.w);
            }
        } else if (kh == 0 && kt == 0) {
            // idle warps write the j<i zeros while others compute
            // (disjoint addresses; no ordering needed). tid in [96,160).
            int j = tid - 96;       // 0..63
            for (int i = j + 1; i < 64; i++)
                og[(size_t)j * DD + i] = 0.f;
        }
    }

    // ---- Epilogue: direct predicated stores (L2 merges spans) ----
    if (work) {
        const float inv = 1.0f / 128.0f;
        const int mrow = wm * 32 + lr;
        const int ncol = wn * 32 + lc * 2;
        const int jrow = kt * 64 + mrow;
        #pragma unroll
        for (int mf = 0; mf < 2; mf++) {
            #pragma unroll
            for (int c2 = 0; c2 < 2; c2++) {
                int j = jrow + mf * 16 + c2 * 8;
                if (j >= WW) continue;
                int m = j - kt * 64;
                float* orow = og + (size_t)j * DD;
                #pragma unroll
                for (int nf = 0; nf < 4; nf++) {
                    #pragma unroll
                    for (int c1 = 0; c1 < 2; c1++) {
                        int n = ncol + nf * 8 + c1;
                        int i = m - n;
                        if (i >= 0 && i < 64)
                            orow[i] = acc[mf][nf][c2 * 2 + c1] * inv;
                    }
                }
            }
        }
    }
}

extern "C" void kernel_launch(void* const* d_in, const int* in_sizes, int n_in,
                              void* d_out, int out_size) {
    const float* left  = (const float*)d_in[0];
    const float* right = (const float*)d_in[1];
    float* out = (float*)d_out;

    cudaFuncSetAttribute(cv_tf32_kernel,
                         cudaFuncAttributeMaxDynamicSharedMemorySize, SMEM_TOTAL);
    dim3 grid(5, 8 * 160);   // (kt, bh)
    cv_tf32_kernel<<<grid, 256, SMEM_TOTAL>>>(left, right, out);
}

// round 11
// speedup vs baseline: 1.6544x; 1.0758x over previous
#include <cuda_runtime.h>
#include <cstdint>

// CostVolume via single tf32 GEMM (mma.sync.m16n8k8.tf32; tcgen05 unavailable
// under virtual arch compute_103).
//
// out[b,h,j,i] = (1/128) * sum_c L[b,h,j,c]*R[b,h,j-i,c], j>=i else 0.
// Per CTA (bh, kt): D[m<128][n<64] = sum_c L[kt*64+m][c]*R[kt*64+n][c];
// out(j=kt*64+m, i=m-n) valid iff 0<=i<64; covered exactly once.
//
// Channel-permutation trick: the K-sum is invariant under any channel
// permutation applied identically to A and B, so tiles are stored in NATURAL
// k-contiguous layout (cp.async-compatible) and the LDS.128 elements are
// re-wired to MMA columns: elements .x/.y feed k-step 2t (cols c / c+4),
// .z/.w feed k-step 2t+1. A is loaded via cp.async (raw f32 bits; HMMA
// truncates to tf32), B via LDG+cvt.rna+STS.128 (keeps rel_err ~4.6e-4).
//
// K processed in 2 sequential halves of 64 reusing one smem buffer
// (60KB/CTA -> 3 CTAs/SM). Row stride 80 floats (64 data + 16 pad):
// LDS.128 phases conflict-free (row-pair offset 80 = 16 mod 32 banks).
// Dead-warp skip: warps wid 3,4 have no valid outputs -> skip mainloop,
// handle the kt==0 j<i zero region instead.
// lds128 MUST be volatile+memory-clobber (same addresses across halves).

#define WW 320
#define CC 128
#define DD 64
#define RSF 80
#define OFF_A 0
#define OFF_B (128 * RSF * 4)               // 40960
#define SMEM_TOTAL (OFF_B + 64 * RSF * 4)   // 61440
#define ROWB (RSF * 4)                      // 320 bytes per row

__device__ __forceinline__ uint32_t smem_u32(const void* p) {
    uint32_t a;
    asm("{ .reg .u64 t; cvta.to.shared.u64 t, %1; cvt.u32.u64 %0, t; }" : "=r"(a) : "l"(p));
    return a;
}
__device__ __forceinline__ uint32_t f2tf32(float x) {
    uint32_t r;
    asm("cvt.rna.tf32.f32 %0, %1;" : "=r"(r) : "f"(x));
    return r;
}
__device__ __forceinline__ void cpasync16(uint32_t dst, const void* src) {
    asm volatile("cp.async.ca.shared.global [%0], [%1], 16;"
                 :: "r"(dst), "l"(src) : "memory");
}
__device__ __forceinline__ void sts128(uint32_t addr, uint32_t x, uint32_t y,
                                       uint32_t z, uint32_t w) {
    asm volatile("st.shared.v4.b32 [%0], {%1,%2,%3,%4};"
                 :: "r"(addr), "r"(x), "r"(y), "r"(z), "r"(w) : "memory");
}
__device__ __forceinline__ uint4 lds128(uint32_t addr) {
    uint4 v;
    asm volatile("ld.shared.v4.b32 {%0,%1,%2,%3}, [%4];"
                 : "=r"(v.x), "=r"(v.y), "=r"(v.z), "=r"(v.w)
                 : "r"(addr) : "memory");
    return v;
}
__device__ __forceinline__ void mma_tf32(float* d, uint32_t a0, uint32_t a1,
                                         uint32_t a2, uint32_t a3,
                                         uint32_t b0, uint32_t b1) {
    asm volatile(
        "mma.sync.aligned.m16n8k8.row.col.f32.tf32.tf32.f32 "
        "{%0,%1,%2,%3}, {%4,%5,%6,%7}, {%8,%9}, {%0,%1,%2,%3};"
        : "+f"(d[0]), "+f"(d[1]), "+f"(d[2]), "+f"(d[3])
        : "r"(a0), "r"(a1), "r"(a2), "r"(a3), "r"(b0), "r"(b1));
}

__global__ __launch_bounds__(256, 3)
void cv_tf32_kernel(const float* __restrict__ L, const float* __restrict__ R,
                    float* __restrict__ out) {
    extern __shared__ char smem[];
    const uint32_t sb = smem_u32(smem);
    const int tid = threadIdx.x;
    const int wid = tid >> 5;
    const int lid = tid & 31;
    const int kt = blockIdx.x;      // 0..4
    const int bh = blockIdx.y;      // 0..1279

    const float* Lg = L + (size_t)bh * WW * CC;
    const float* Rg = R + (size_t)bh * WW * CC;
    float* og = out + (size_t)bh * WW * DD;

    const int wm = wid & 3;
    const int wn = wid >> 2;
    const bool work = (wid != 3) && (wid != 4);   // band-dead warps
    const int lr = lid >> 2;
    const int lc = lid & 3;
    const uint32_t aBase = sb + OFF_A + (uint32_t)((wm * 32 + lr) * ROWB + lc * 16);
    const uint32_t bBase = sb + OFF_B + (uint32_t)((wn * 32 + lr) * ROWB + lc * 16);
    const uint32_t R8 = 8 * ROWB;   // 2560

    const int g  = tid & 15;        // 16B chunk: channels 4g..4g+3 of the half
    const int m0 = tid >> 4;        // starting row, stride 16

    float acc[2][4][4];
    #pragma unroll
    for (int mf = 0; mf < 2; mf++)
        #pragma unroll
        for (int nf = 0; nf < 4; nf++)
            #pragma unroll
            for (int c = 0; c < 4; c++) acc[mf][nf][c] = 0.f;

    #pragma unroll
    for (int kh = 0; kh < 2; kh++) {
        if (kh) __syncthreads();    // drain readers before overwriting smem

        // ---- Prologue: A via cp.async (raw f32), B via LDG+cvt.rna+STS.128 ----
        {
            const int csrc = kh * 64 + g * 4;
            // A: 8 x cp.async, rows m0+16it (clamped at 319)
            uint32_t dstA = sb + OFF_A + (uint32_t)(m0 * ROWB + g * 16);
            #pragma unroll
            for (int it = 0; it < 8; it++) {
                int j = kt * 64 + m0 + it * 16;
                if (j > WW - 1) j = WW - 1;     // overrun rows pruned at store
                cpasync16(dstA, Lg + (size_t)j * CC + csrc);
                dstA += 16 * ROWB;
            }
            asm volatile("cp.async.commit_group;" ::: "memory");
            // B: LDG.128 -> cvt.rna x4 -> STS.128 (overlaps with async copies)
            uint32_t dstB = sb + OFF_B + (uint32_t)(m0 * ROWB + g * 16);
            const float4* srcB = (const float4*)(Rg + (size_t)(kt * 64 + m0) * CC + csrc);
            #pragma unroll
            for (int it = 0; it < 4; it++) {
                float4 v = __ldg(srcB);
                sts128(dstB, f2tf32(v.x), f2tf32(v.y), f2tf32(v.z), f2tf32(v.w));
                srcB += 16 * (CC / 4);
                dstB += 16 * ROWB;
            }
            asm volatile("cp.async.wait_group 0;" ::: "memory");
        }
        __syncthreads();

        if (work) {
            // ---- Mainloop: warp tile 32x32, 4 t-iters per half ----
            // LDS.128 elements: .x/.y -> k-step 2t (cols c / c+4), .z/.w -> 2t+1.
            #pragma unroll
            for (int t = 0; t < 4; t++) {
                const uint32_t ko = t * 64;
                uint4 a0 = lds128(aBase + ko);
                uint4 a1 = lds128(aBase + R8 + ko);
                uint4 a2 = lds128(aBase + 2 * R8 + ko);
                uint4 a3 = lds128(aBase + 3 * R8 + ko);
                uint4 b0 = lds128(bBase + ko);
                uint4 b1 = lds128(bBase + R8 + ko);
                uint4 b2 = lds128(bBase + 2 * R8 + ko);
                uint4 b3 = lds128(bBase + 3 * R8 + ko);
                mma_tf32(acc[0][0], a0.x, a1.x, a0.y, a1.y, b0.x, b0.y);
                mma_tf32(acc[0][1], a0.x, a1.x, a0.y, a1.y, b1.x, b1.y);
                mma_tf32(acc[0][2], a0.x, a1.x, a0.y, a1.y, b2.x, b2.y);
                mma_tf32(acc[0][3], a0.x, a1.x, a0.y, a1.y, b3.x, b3.y);
                mma_tf32(acc[1][0], a2.x, a3.x, a2.y, a3.y, b0.x, b0.y);
                mma_tf32(acc[1][1], a2.x, a3.x, a2.y, a3.y, b1.x, b1.y);
                mma_tf32(acc[1][2], a2.x, a3.x, a2.y, a3.y, b2.x, b2.y);
                mma_tf32(acc[1][3], a2.x, a3.x, a2.y, a3.y, b3.x, b3.y);
                mma_tf32(acc[0][0], a0.z, a1.z, a0.w, a1.w, b0.z, b0.w);
                mma_tf32(acc[0][1], a0.z, a1.z, a0.w, a1.w, b1.z, b1.w);
                mma_tf32(acc[0][2], a0.z, a1.z, a0.w, a1.w, b2.z, b2.w);
                mma_tf32(acc[0][3], a0.z, a1.z, a0.w, a1.w, b3.z, b3.w);
                mma_tf32(acc[1][0], a2.z, a3.z, a2.w, a3.w, b0.z, b0.w);
                mma_tf32(acc[1][1], a2.z, a3.z, a2.w, a3.w, b1.z, b1.w);
                mma_tf32(acc[1][2], a2.z, a3.z, a2.w, a3.w, b2.z, b2.w);
                mma_tf32(acc[1][3], a2.z, a3.z, a2.w, a3.w, b3.z, b3.w);
            }
        } else if (kh == 0 && kt == 0) {
            // idle warps write the j<i zeros concurrently (disjoint addresses)
            int j = tid - 96;       // tid in [96,160) -> j 0..63
            for (int i = j + 1; i < 64; i++)
                og[(size_t)j * DD + i] = 0.f;
        }
    }

    // ---- Epilogue: direct predicated stores (L2 merges spans) ----
    if (work) {
        const float inv = 1.0f / 128.0f;
        const int mrow = wm * 32 + lr;
        const int ncol = wn * 32 + lc * 2;
        const int jrow = kt * 64 + mrow;
        #pragma unroll
        for (int mf = 0; mf < 2; mf++) {
            #pragma unroll
            for (int c2 = 0; c2 < 2; c2++) {
                int j = jrow + mf * 16 + c2 * 8;
                if (j >= WW) continue;
                int m = j - kt * 64;
                float* orow = og + (size_t)j * DD;
                #pragma unroll
                for (int nf = 0; nf < 4; nf++) {
                    #pragma unroll
                    for (int c1 = 0; c1 < 2; c1++) {
                        int n = ncol + nf * 8 + c1;
                        int i = m - n;
                        if (i >= 0 && i < 64)
                            orow[i] = acc[mf][nf][c2 * 2 + c1] * inv;
                    }
                }
            }
        }
    }
}

extern "C" void kernel_launch(void* const* d_in, const int* in_sizes, int n_in,
                              void* d_out, int out_size) {
    const float* left  = (const float*)d_in[0];
    const float* right = (const float*)d_in[1];
    float* out = (float*)d_out;

    cudaFuncSetAttribute(cv_tf32_kernel,
                         cudaFuncAttributeMaxDynamicSharedMemorySize, SMEM_TOTAL);
    dim3 grid(5, 8 * 160);   // (kt, bh)
    cv_tf32_kernel<<<grid, 256, SMEM_TOTAL>>>(left, right, out);
}